// round 11
// baseline (speedup 1.0000x reference)
#include <cuda_runtime.h>
#include <cuda_bf16.h>
#include <cstdint>
#include <cstring>
#include <math.h>

typedef unsigned short ushort_t;

// Shapes
#define BATCH 64
#define ED 512
#define RES 28
#define HW 784
#define WS 7
#define NW_TOT 1024
#define NH 8
#define KD 16
#define DHEAD 64
#define QKV_OUT 96
#define NTOK 49
#define NTOKP 56

#define NTOT 50176        // 64*784
#define NPROJ 57344       // 1024*56

// Scratch (device globals)
__device__ float    g_af[ED * NTOT];
__device__ float    g_bf[ED * NTOT];
__device__ ushort_t g_ah[ED * NTOT];
__device__ ushort_t g_al[ED * NTOT];
__device__ ushort_t g_hh[2 * ED * NTOT];
__device__ ushort_t g_hl[2 * ED * NTOT];
__device__ ushort_t g_ch[ED * NPROJ];
__device__ ushort_t g_cl[ED * NPROJ];
__device__ ushort_t g_w1h[1024 * 512], g_w1l[1024 * 512];
__device__ ushort_t g_w2h[512 * 1024], g_w2l[512 * 1024];
__device__ ushort_t g_w1bh[1024 * 512], g_w1bl[1024 * 512];
__device__ ushort_t g_w2bh[512 * 1024], g_w2bl[512 * 1024];
__device__ ushort_t g_pjh[512 * 512], g_pjl[512 * 512];

__device__ __forceinline__ float hswish(float x) {
    return x * fminf(fmaxf(x + 3.f, 0.f), 6.f) * (1.f / 6.f);
}
__device__ __forceinline__ void split2(float v, ushort_t& h, ushort_t& l) {
    __nv_bfloat16 hb = __float2bfloat16_rn(v);
    float hf = __bfloat162float(hb);
    __nv_bfloat16 lb = __float2bfloat16_rn(v - hf);
    memcpy(&h, &hb, 2);
    memcpy(&l, &lb, 2);
}
__device__ __forceinline__ uint32_t smem_u32(const void* p) {
    return (uint32_t)__cvta_generic_to_shared(p);
}
__device__ __forceinline__ void cpasync16(uint32_t dst, const void* src) {
    asm volatile("cp.async.cg.shared.global [%0], [%1], 16;" :: "r"(dst), "l"(src));
}
__device__ __forceinline__ void mma_bf16(float* c, const uint32_t* a, const uint32_t* b)
{
    asm volatile(
        "mma.sync.aligned.m16n8k16.row.col.f32.bf16.bf16.f32 "
        "{%0,%1,%2,%3}, {%4,%5,%6,%7}, {%8,%9}, {%0,%1,%2,%3};\n"
        : "+f"(c[0]), "+f"(c[1]), "+f"(c[2]), "+f"(c[3])
        : "r"(a[0]), "r"(a[1]), "r"(a[2]), "r"(a[3]), "r"(b[0]), "r"(b[1]));
}
__device__ __forceinline__ void ldsm4(uint32_t& r0, uint32_t& r1,
                                      uint32_t& r2, uint32_t& r3, uint32_t addr)
{
    asm volatile("ldmatrix.sync.aligned.m8n8.x4.shared.b16 {%0,%1,%2,%3}, [%4];"
                 : "=r"(r0), "=r"(r1), "=r"(r2), "=r"(r3) : "r"(addr));
}
__device__ __forceinline__ void ldsm4t(uint32_t& r0, uint32_t& r1,
                                       uint32_t& r2, uint32_t& r3, uint32_t addr)
{
    asm volatile("ldmatrix.sync.aligned.m8n8.x4.trans.shared.b16 {%0,%1,%2,%3}, [%4];"
                 : "=r"(r0), "=r"(r1), "=r"(r2), "=r"(r3) : "r"(addr));
}

// ---------------------------------------------------------------------------
__global__ void __launch_bounds__(256) pack_weights_kernel(
    const float* __restrict__ W, ushort_t* __restrict__ Ph,
    ushort_t* __restrict__ Pl, int n)
{
    int i = blockIdx.x * 256 + threadIdx.x;
    if (i < n) {
        ushort_t h, l;
        split2(W[i], h, l);
        Ph[i] = h; Pl[i] = l;
    }
}

// ---------------------------------------------------------------------------
template<bool IN_CM>
__global__ void __launch_bounds__(256) dwconv_res_kernel(
    const float* __restrict__ x, const float* __restrict__ w,
    const float* __restrict__ bias, float* __restrict__ out,
    ushort_t* __restrict__ oh, ushort_t* __restrict__ ol)
{
    int bc = blockIdx.y;
    int c = bc & (ED - 1);
    int b = bc >> 9;
    int pos = blockIdx.x * 256 + threadIdx.x;
    if (pos >= HW) return;
    int h = pos / RES, ww = pos % RES;
    const float* xp = IN_CM ? (x + (size_t)c * NTOT + (size_t)b * HW)
                            : (x + (size_t)bc * HW);
    const float* wp = w + c * 9;
    float acc = bias[c];
#pragma unroll
    for (int dy = 0; dy < 3; dy++) {
        int yy = h + dy - 1;
        if (yy < 0 || yy >= RES) continue;
#pragma unroll
        for (int dx = 0; dx < 3; dx++) {
            int xx = ww + dx - 1;
            if (xx < 0 || xx >= RES) continue;
            acc += xp[yy * RES + xx] * wp[dy * 3 + dx];
        }
    }
    float r = xp[pos] + acc;
    size_t o = (size_t)c * NTOT + (size_t)b * HW + pos;
    out[o] = r;
    ushort_t hh, ll;
    split2(r, hh, ll);
    oh[o] = hh; ol[o] = ll;
}

// ---------------------------------------------------------------------------
// HMMA GEMM, CTA 128x128, K-chunk 32, cp.async double buffer, hi/lo planes.
// GRID: blockIdx.x = M tile (fastest), blockIdx.y = N tile -> CTAs sharing the
// same B column-tile are consecutive bids (co-resident wave) => B served by L2.
// ---------------------------------------------------------------------------
template<int MODE>
__global__ void __launch_bounds__(256, 2) gemm_cp_kernel(
    const ushort_t* __restrict__ Awh, const ushort_t* __restrict__ Awl,
    const ushort_t* __restrict__ Bh,  const ushort_t* __restrict__ Bl,
    const float* __restrict__ bias, const float* __restrict__ resid,
    float* __restrict__ Cf, ushort_t* __restrict__ Chh, ushort_t* __restrict__ Chl,
    int M, int NB, int K)
{
    extern __shared__ char sm[];
    int t = threadIdx.x;
    int warp = t >> 5, lane = t & 31;
    int wm = warp & 1, wn = warp >> 1;
    int m0w = wm * 64, n0w = wn * 32;
    int g = lane >> 2, tig = lane & 3;
    int m0 = blockIdx.x * 128, n0 = blockIdx.y * 128;
    uint32_t sbase = smem_u32(sm);

    float acc[4][4][4];
#pragma unroll
    for (int i = 0; i < 4; i++)
#pragma unroll
        for (int j = 0; j < 4; j++)
#pragma unroll
            for (int q = 0; q < 4; q++) acc[i][j][q] = 0.f;

    auto stage = [&](int k0, int buf) {
        uint32_t soff = sbase + buf * 32768;
#pragma unroll
        for (int i = 0; i < 2; i++) {
            int idx = t + i * 256;
            int m = idx >> 2, c = idx & 3;
            uint32_t d = soff + m * 64 + ((c ^ ((m >> 1) & 3)) << 4);
            cpasync16(d, Awh + (size_t)(m0 + m) * K + k0 + c * 8);
            cpasync16(d + 8192, Awl + (size_t)(m0 + m) * K + k0 + c * 8);
        }
#pragma unroll
        for (int i = 0; i < 2; i++) {
            int idx = t + i * 256;
            int k = idx >> 4, c = idx & 15;
            uint32_t d = soff + 16384 + k * 256 + ((c ^ (k & 7)) << 4);
            cpasync16(d, Bh + (size_t)(k0 + k) * NB + n0 + c * 8);
            cpasync16(d + 8192, Bl + (size_t)(k0 + k) * NB + n0 + c * 8);
        }
        asm volatile("cp.async.commit_group;" ::: "memory");
    };

    stage(0, 0);
    int nk = K >> 5;
    for (int kc = 0; kc < nk; kc++) {
        if (kc + 1 < nk) {
            stage((kc + 1) << 5, (kc + 1) & 1);
            asm volatile("cp.async.wait_group 1;" ::: "memory");
        } else {
            asm volatile("cp.async.wait_group 0;" ::: "memory");
        }
        __syncthreads();
        uint32_t soff = sbase + (kc & 1) * 32768;
#pragma unroll
        for (int kk = 0; kk < 32; kk += 16) {
            uint32_t bh[4][2], bl[4][2];
#pragma unroll
            for (int j2 = 0; j2 < 2; j2++) {
                int krow = kk + (lane & 15);
                int cn = wn * 4 + j2 * 2 + (lane >> 4);
                uint32_t a = soff + 16384 + krow * 256 + ((cn ^ (krow & 7)) << 4);
                ldsm4t(bh[j2*2][0], bh[j2*2][1], bh[j2*2+1][0], bh[j2*2+1][1], a);
                ldsm4t(bl[j2*2][0], bl[j2*2][1], bl[j2*2+1][0], bl[j2*2+1][1], a + 8192);
            }
#pragma unroll
            for (int i = 0; i < 4; i++) {
                int row = m0w + i * 16 + (lane & 15);
                int c = (kk >> 3) + (lane >> 4);
                uint32_t a = soff + row * 64 + ((c ^ ((row >> 1) & 3)) << 4);
                uint32_t ah[4], al[4];
                ldsm4(ah[0], ah[1], ah[2], ah[3], a);
                ldsm4(al[0], al[1], al[2], al[3], a + 8192);
#pragma unroll
                for (int j = 0; j < 4; j++) {
                    mma_bf16(acc[i][j], ah, bh[j]);
                    mma_bf16(acc[i][j], ah, bl[j]);
                    mma_bf16(acc[i][j], al, bh[j]);
                }
            }
        }
        __syncthreads();
    }

    // Epilogue
#pragma unroll
    for (int i = 0; i < 4; i++) {
        int r0 = m0 + m0w + i * 16 + g;
        int r1 = r0 + 8;
        float b0v = bias[r0], b1v = bias[r1];
#pragma unroll
        for (int j = 0; j < 4; j++) {
            int cb = n0 + n0w + j * 8 + tig * 2;
            float v00 = acc[i][j][0] + b0v, v01 = acc[i][j][1] + b0v;
            float v10 = acc[i][j][2] + b1v, v11 = acc[i][j][3] + b1v;
            if (MODE == 0) {
                ushort_t h0, l0, h1, l1;
                split2(hswish(v00), h0, l0);
                split2(hswish(v01), h1, l1);
                *(uint32_t*)&Chh[(size_t)r0 * NB + cb] = (uint32_t)h0 | ((uint32_t)h1 << 16);
                *(uint32_t*)&Chl[(size_t)r0 * NB + cb] = (uint32_t)l0 | ((uint32_t)l1 << 16);
                split2(hswish(v10), h0, l0);
                split2(hswish(v11), h1, l1);
                *(uint32_t*)&Chh[(size_t)r1 * NB + cb] = (uint32_t)h0 | ((uint32_t)h1 << 16);
                *(uint32_t*)&Chl[(size_t)r1 * NB + cb] = (uint32_t)l0 | ((uint32_t)l1 << 16);
            } else if (MODE == 1) {
                size_t o0 = (size_t)r0 * NB + cb;
                size_t o1 = (size_t)r1 * NB + cb;
                float2 rr0 = *(const float2*)&resid[o0];
                float2 rr1 = *(const float2*)&resid[o1];
                *(float2*)&Cf[o0] = make_float2(v00 + rr0.x, v01 + rr0.y);
                *(float2*)&Cf[o1] = make_float2(v10 + rr1.x, v11 + rr1.y);
            } else if (MODE == 2) {
                float vs[4] = {v00, v01, v10, v11};
#pragma unroll
                for (int q = 0; q < 4; q++) {
                    int col = cb + (q & 1);
                    int r = (q < 2) ? r0 : r1;
                    int win = col / NTOKP, tok = col % NTOKP;
                    if (tok < NTOK) {
                        int b = win >> 4, wy = (win >> 2) & 3, wx = win & 3;
                        int iy = tok / WS, ix = tok % WS;
                        size_t o = (size_t)r * NTOT + (size_t)b * HW
                                 + (wy * WS + iy) * RES + (wx * WS + ix);
                        Cf[o] = Cf[o] + vs[q];
                    }
                }
            } else {
                int b = cb / HW, pos = cb % HW;
                size_t o0 = (size_t)r0 * NB + cb;
                size_t o1 = (size_t)r1 * NB + cb;
                float2 rr0 = *(const float2*)&resid[o0];
                float2 rr1 = *(const float2*)&resid[o1];
                *(float2*)&Cf[((size_t)b * ED + r0) * HW + pos] =
                    make_float2(v00 + rr0.x, v01 + rr0.y);
                *(float2*)&Cf[((size_t)b * ED + r1) * HW + pos] =
                    make_float2(v10 + rr1.x, v11 + rr1.y);
            }
        }
    }
}

// ---------------------------------------------------------------------------
// Cascaded window attention (vectorized, coalesced output stores)
// ---------------------------------------------------------------------------
#define SP_OFF   0
#define Y_OFF    (SP_OFF + 49 * 68)
#define KT_OFF   (Y_OFF + 96 * 52)
#define QT_OFF   (KT_OFF + 49 * 20)
#define ATT_OFF  (QT_OFF + 49 * 20)
#define WSM_OFF  (ATT_OFF + 49 * 52)
#define BSM_OFF  (WSM_OFF + 96 * 68)
#define BIA_OFF  (BSM_OFF + 96)
#define ATTN_SMEM_FLOATS (BIA_OFF + 64)
#define ATTN_SMEM_BYTES  (ATTN_SMEM_FLOATS * 4)

__global__ void __launch_bounds__(256) attn_kernel(
    const float* __restrict__ xin,
    const float* __restrict__ qkv_w,
    const float* __restrict__ qkv_b,
    const float* __restrict__ w7, const float* __restrict__ b7,
    const float* __restrict__ w5, const float* __restrict__ b5,
    const float* __restrict__ w3, const float* __restrict__ b3,
    const float* __restrict__ attn_bias,
    ushort_t* __restrict__ oh, ushort_t* __restrict__ ol)
{
    extern __shared__ float smem[];
    float* spT = smem + SP_OFF;
    float* y   = smem + Y_OFF;
    float* kT  = smem + KT_OFF;
    float* qcT = smem + QT_OFF;
    float* att = smem + ATT_OFF;
    float* wsm = smem + WSM_OFF;
    float* bsm = smem + BSM_OFF;
    float* bia = smem + BIA_OFF;

    int w = blockIdx.x;
    int b = w >> 4, wy = (w >> 2) & 3, wx = w & 3;
    int t = threadIdx.x;
    int warp = t >> 5, lane = t & 31;

    for (int i = t; i < 96 * 3; i += 256)
        y[(i / 3) * 52 + 49 + i % 3] = 0.f;

    for (int head = 0; head < NH; head++) {
        for (int i = t; i < QKV_OUT * DHEAD; i += 256) {
            int m = i >> 6, c = i & 63;
            wsm[m * 68 + c] = qkv_w[head * QKV_OUT * DHEAD + i];
        }
        if (t < QKV_OUT) bsm[t] = qkv_b[head * QKV_OUT + t];
        if (t < NTOK)    bia[t] = attn_bias[head * NTOK + t];
        for (int i = t; i < DHEAD * NTOK; i += 256) {
            int c = i / NTOK, n = i % NTOK;
            int iy = n / WS, ix = n % WS;
            float xv = xin[(size_t)(head * DHEAD + c) * NTOT + (size_t)b * HW
                           + (wy * WS + iy) * RES + (wx * WS + ix)];
            spT[n * 68 + c] = (head == 0) ? xv : spT[n * 68 + c] + xv;
        }
        __syncthreads();

        // QKV
        for (int it = t; it < 13 * 96; it += 256) {
            int gq = it / 96, m = it % 96;
            int n0 = gq * 4;
            float a0 = bsm[m], a1 = a0, a2 = a0, a3 = a0;
            const float* wr = &wsm[m * 68];
#pragma unroll
            for (int c4 = 0; c4 < 16; c4++) {
                float4 wv = *(const float4*)&wr[c4 * 4];
                float4 s0 = *(const float4*)&spT[(n0 + 0) * 68 + c4 * 4];
                float4 s1 = *(const float4*)&spT[(n0 + 1) * 68 + c4 * 4];
                float4 s2 = *(const float4*)&spT[(n0 + 2) * 68 + c4 * 4];
                float4 s3 = *(const float4*)&spT[(n0 + 3) * 68 + c4 * 4];
                a0 += wv.x * s0.x + wv.y * s0.y + wv.z * s0.z + wv.w * s0.w;
                a1 += wv.x * s1.x + wv.y * s1.y + wv.z * s1.z + wv.w * s1.w;
                a2 += wv.x * s2.x + wv.y * s2.y + wv.z * s2.z + wv.w * s2.w;
                a3 += wv.x * s3.x + wv.y * s3.y + wv.z * s3.z + wv.w * s3.w;
            }
            float av[4] = {a0, a1, a2, a3};
#pragma unroll
            for (int j = 0; j < 4; j++) {
                int n = n0 + j;
                if (n < NTOK) {
                    y[m * 52 + n] = av[j];
                    if (m >= KD && m < 2 * KD) kT[n * 20 + m - KD] = av[j];
                }
            }
        }
        __syncthreads();

        // depthwise conv on q
        int ksz; const float* dw; const float* db;
        if (head == 0)      { ksz = 7; dw = w7; db = b7; }
        else if (head == 1) { ksz = 5; dw = w5; db = b5; }
        else                { ksz = 3; dw = w3 + (head - 2) * KD * 9; db = b3 + (head - 2) * KD; }
        int pad = ksz >> 1;
        for (int it = t; it < KD * NTOK; it += 256) {
            int c = it / NTOK, n = it % NTOK;
            int iy = n / WS, ix = n % WS;
            float acc = db[c];
            const float* yr = &y[c * 52];
            const float* dwc = dw + c * ksz * ksz;
            for (int dy = 0; dy < ksz; dy++) {
                int yy = iy + dy - pad;
                if (yy < 0 || yy >= WS) continue;
                for (int dx = 0; dx < ksz; dx++) {
                    int xx = ix + dx - pad;
                    if (xx < 0 || xx >= WS) continue;
                    acc += yr[yy * WS + xx] * dwc[dy * ksz + dx];
                }
            }
            qcT[n * 20 + c] = acc;
        }
        __syncthreads();

        // scores
        for (int it = t; it < 49 * 52; it += 256) {
            int n = it / 52, m = it % 52;
            if (m >= NTOK) { att[it] = 0.f; continue; }
            const float* qr = &qcT[n * 20];
            const float* kr = &kT[m * 20];
            float acc = 0.f;
#pragma unroll
            for (int c4 = 0; c4 < 4; c4++) {
                float4 qv = *(const float4*)&qr[c4 * 4];
                float4 kv = *(const float4*)&kr[c4 * 4];
                acc += qv.x * kv.x + qv.y * kv.y + qv.z * kv.z + qv.w * kv.w;
            }
            int ny = n / WS, nx = n % WS, my = m / WS, mx = m % WS;
            att[it] = acc * 0.25f + bia[abs(ny - my) * WS + abs(nx - mx)];
        }
        __syncthreads();

        // softmax: warp per row
        for (int r = warp; r < NTOK; r += 8) {
            float v0 = att[r * 52 + lane];
            float v1 = (lane + 32 < NTOK) ? att[r * 52 + lane + 32] : -1e30f;
            float mx = fmaxf(v0, v1);
#pragma unroll
            for (int s = 16; s; s >>= 1) mx = fmaxf(mx, __shfl_xor_sync(~0u, mx, s));
            float e0 = expf(v0 - mx);
            float e1 = (lane + 32 < NTOK) ? expf(v1 - mx) : 0.f;
            float sum = e0 + e1;
#pragma unroll
            for (int s = 16; s; s >>= 1) sum += __shfl_xor_sync(~0u, sum, s);
            float inv = 1.f / sum;
            att[r * 52 + lane] = e0 * inv;
            if (lane + 32 < NTOK) att[r * 52 + lane + 32] = e1 * inv;
        }
        __syncthreads();

        // AV
        size_t obase = (size_t)(head * DHEAD) * NPROJ + (size_t)w * NTOKP;
        for (int it = t; it < 16 * NTOK; it += 256) {
            int dg = it / NTOK, n = it % NTOK;
            int d0 = dg * 4;
            float a0 = 0.f, a1 = 0.f, a2 = 0.f, a3 = 0.f;
            const float* ar = &att[n * 52];
#pragma unroll
            for (int m4 = 0; m4 < 13; m4++) {
                float4 av = *(const float4*)&ar[m4 * 4];
                float4 v0 = *(const float4*)&y[(32 + d0 + 0) * 52 + m4 * 4];
                float4 v1 = *(const float4*)&y[(32 + d0 + 1) * 52 + m4 * 4];
                float4 v2 = *(const float4*)&y[(32 + d0 + 2) * 52 + m4 * 4];
                float4 v3 = *(const float4*)&y[(32 + d0 + 3) * 52 + m4 * 4];
                a0 += av.x * v0.x + av.y * v0.y + av.z * v0.z + av.w * v0.w;
                a1 += av.x * v1.x + av.y * v1.y + av.z * v1.z + av.w * v1.w;
                a2 += av.x * v2.x + av.y * v2.y + av.z * v2.z + av.w * v2.w;
                a3 += av.x * v3.x + av.y * v3.y + av.z * v3.z + av.w * v3.w;
            }
            float av4[4] = {a0, a1, a2, a3};
#pragma unroll
            for (int jj = 0; jj < 4; jj++) {
                int d = d0 + jj;
                spT[n * 68 + d] = av4[jj];
                ushort_t hh, ll;
                split2(hswish(av4[jj]), hh, ll);
                oh[obase + (size_t)d * NPROJ + n] = hh;
                ol[obase + (size_t)d * NPROJ + n] = ll;
            }
        }
        for (int it = t; it < DHEAD * (NTOKP - NTOK); it += 256) {
            int p = it / DHEAD, d = it % DHEAD;
            oh[obase + (size_t)d * NPROJ + NTOK + p] = 0;
            ol[obase + (size_t)d * NPROJ + NTOK + p] = 0;
        }
        __syncthreads();
    }
}

// ---------------------------------------------------------------------------
extern "C" void kernel_launch(void* const* d_in, const int* in_sizes, int n_in,
                              void* d_out, int out_size)
{
    const float* x        = (const float*)d_in[0];
    const float* dw0_w    = (const float*)d_in[1];
    const float* dw0_b    = (const float*)d_in[2];
    const float* ffn0_w1  = (const float*)d_in[3];
    const float* ffn0_b1  = (const float*)d_in[4];
    const float* ffn0_w2  = (const float*)d_in[5];
    const float* ffn0_b2  = (const float*)d_in[6];
    const float* qkv_w    = (const float*)d_in[7];
    const float* qkv_b    = (const float*)d_in[8];
    const float* dwq_w7   = (const float*)d_in[9];
    const float* dwq_b7   = (const float*)d_in[10];
    const float* dwq_w5   = (const float*)d_in[11];
    const float* dwq_b5   = (const float*)d_in[12];
    const float* dwq_w3   = (const float*)d_in[13];
    const float* dwq_b3   = (const float*)d_in[14];
    const float* attn_bias= (const float*)d_in[15];
    const float* proj_w   = (const float*)d_in[16];
    const float* proj_b   = (const float*)d_in[17];
    const float* dw1_w    = (const float*)d_in[18];
    const float* dw1_b    = (const float*)d_in[19];
    const float* ffn1_w1  = (const float*)d_in[20];
    const float* ffn1_b1  = (const float*)d_in[21];
    const float* ffn1_w2  = (const float*)d_in[22];
    const float* ffn1_b2  = (const float*)d_in[23];

    float *paf, *pbf;
    ushort_t *pah, *pal, *phh, *phl, *pch, *pcl;
    ushort_t *pw1h, *pw1l, *pw2h, *pw2l, *pw1bh, *pw1bl, *pw2bh, *pw2bl, *ppjh, *ppjl;
    cudaGetSymbolAddress((void**)&paf, g_af);
    cudaGetSymbolAddress((void**)&pbf, g_bf);
    cudaGetSymbolAddress((void**)&pah, g_ah);
    cudaGetSymbolAddress((void**)&pal, g_al);
    cudaGetSymbolAddress((void**)&phh, g_hh);
    cudaGetSymbolAddress((void**)&phl, g_hl);
    cudaGetSymbolAddress((void**)&pch, g_ch);
    cudaGetSymbolAddress((void**)&pcl, g_cl);
    cudaGetSymbolAddress((void**)&pw1h, g_w1h);
    cudaGetSymbolAddress((void**)&pw1l, g_w1l);
    cudaGetSymbolAddress((void**)&pw2h, g_w2h);
    cudaGetSymbolAddress((void**)&pw2l, g_w2l);
    cudaGetSymbolAddress((void**)&pw1bh, g_w1bh);
    cudaGetSymbolAddress((void**)&pw1bl, g_w1bl);
    cudaGetSymbolAddress((void**)&pw2bh, g_w2bh);
    cudaGetSymbolAddress((void**)&pw2bl, g_w2bl);
    cudaGetSymbolAddress((void**)&ppjh, g_pjh);
    cudaGetSymbolAddress((void**)&ppjl, g_pjl);

    cudaFuncSetAttribute(attn_kernel, cudaFuncAttributeMaxDynamicSharedMemorySize, ATTN_SMEM_BYTES);
    cudaFuncSetAttribute(gemm_cp_kernel<0>, cudaFuncAttributeMaxDynamicSharedMemorySize, 65536);
    cudaFuncSetAttribute(gemm_cp_kernel<1>, cudaFuncAttributeMaxDynamicSharedMemorySize, 65536);
    cudaFuncSetAttribute(gemm_cp_kernel<2>, cudaFuncAttributeMaxDynamicSharedMemorySize, 65536);
    cudaFuncSetAttribute(gemm_cp_kernel<3>, cudaFuncAttributeMaxDynamicSharedMemorySize, 65536);

    // Weight pre-split
    pack_weights_kernel<<<2048, 256>>>(ffn0_w1, pw1h, pw1l, 1024 * 512);
    pack_weights_kernel<<<2048, 256>>>(ffn0_w2, pw2h, pw2l, 512 * 1024);
    pack_weights_kernel<<<2048, 256>>>(ffn1_w1, pw1bh, pw1bl, 1024 * 512);
    pack_weights_kernel<<<2048, 256>>>(ffn1_w2, pw2bh, pw2bl, 512 * 1024);
    pack_weights_kernel<<<1024, 256>>>(proj_w, ppjh, ppjl, 512 * 512);

    dim3 dwgrid((HW + 255) / 256, BATCH * ED);

    dwconv_res_kernel<false><<<dwgrid, 256>>>(x, dw0_w, dw0_b, paf, pah, pal);
    // grid: (Mtiles, Ntiles) — M fastest so B-sharing CTAs are co-resident
    gemm_cp_kernel<0><<<dim3(8, NTOT / 128), 256, 65536>>>(
        pw1h, pw1l, pah, pal, ffn0_b1, nullptr, nullptr, phh, phl, 1024, NTOT, 512);
    gemm_cp_kernel<1><<<dim3(4, NTOT / 128), 256, 65536>>>(
        pw2h, pw2l, phh, phl, ffn0_b2, paf, pbf, nullptr, nullptr, 512, NTOT, 1024);
    attn_kernel<<<NW_TOT, 256, ATTN_SMEM_BYTES>>>(pbf, qkv_w, qkv_b, dwq_w7, dwq_b7,
        dwq_w5, dwq_b5, dwq_w3, dwq_b3, attn_bias, pch, pcl);
    gemm_cp_kernel<2><<<dim3(4, NPROJ / 128), 256, 65536>>>(
        ppjh, ppjl, pch, pcl, proj_b, nullptr, pbf, nullptr, nullptr, 512, NPROJ, 512);
    dwconv_res_kernel<true><<<dwgrid, 256>>>(pbf, dw1_w, dw1_b, paf, pah, pal);
    gemm_cp_kernel<0><<<dim3(8, NTOT / 128), 256, 65536>>>(
        pw1bh, pw1bl, pah, pal, ffn1_b1, nullptr, nullptr, phh, phl, 1024, NTOT, 512);
    gemm_cp_kernel<3><<<dim3(4, NTOT / 128), 256, 65536>>>(
        pw2bh, pw2bl, phh, phl, ffn1_b2, paf, (float*)d_out, nullptr, nullptr, 512, NTOT, 1024);
}

// round 14
// speedup vs baseline: 1.1564x; 1.1564x over previous
#include <cuda_runtime.h>
#include <cuda_fp16.h>
#include <cstdint>
#include <cstring>
#include <math.h>

typedef unsigned short ushort_t;

// Shapes
#define BATCH 64
#define ED 512
#define RES 28
#define HW 784
#define WS 7
#define NW_TOT 1024
#define NH 8
#define KD 16
#define DHEAD 64
#define QKV_OUT 96
#define NTOK 49
#define NTOKP 56

#define NTOT 50176        // 64*784
#define NPROJ 57344       // 1024*56

// Scratch (device globals)
__device__ float    g_af[ED * NTOT];
__device__ float    g_bf[ED * NTOT];
__device__ ushort_t g_ah[ED * NTOT];        // activation hi plane (fp16)
__device__ ushort_t g_al[ED * NTOT];        // activation lo plane (fp16)
__device__ ushort_t g_hh[2 * ED * NTOT];
__device__ ushort_t g_hl[2 * ED * NTOT];
__device__ ushort_t g_ch[ED * NPROJ];
__device__ ushort_t g_cl[ED * NPROJ];
__device__ ushort_t g_w1h[1024 * 512];      // weight hi planes only (fp16)
__device__ ushort_t g_w2h[512 * 1024];
__device__ ushort_t g_w1bh[1024 * 512];
__device__ ushort_t g_w2bh[512 * 1024];
__device__ ushort_t g_pjh[512 * 512];

__device__ __forceinline__ float hswish(float x) {
    return x * fminf(fmaxf(x + 3.f, 0.f), 6.f) * (1.f / 6.f);
}
// fp16 split: v = h + l (h,l fp16)
__device__ __forceinline__ void split2(float v, ushort_t& h, ushort_t& l) {
    __half hb = __float2half_rn(v);
    float hf = __half2float(hb);
    __half lb = __float2half_rn(v - hf);
    memcpy(&h, &hb, 2);
    memcpy(&l, &lb, 2);
}
__device__ __forceinline__ uint32_t smem_u32(const void* p) {
    return (uint32_t)__cvta_generic_to_shared(p);
}
__device__ __forceinline__ void cpasync16(uint32_t dst, const void* src) {
    asm volatile("cp.async.cg.shared.global [%0], [%1], 16;" :: "r"(dst), "l"(src));
}
__device__ __forceinline__ void mma_f16(float* c, const uint32_t* a, const uint32_t* b)
{
    asm volatile(
        "mma.sync.aligned.m16n8k16.row.col.f32.f16.f16.f32 "
        "{%0,%1,%2,%3}, {%4,%5,%6,%7}, {%8,%9}, {%0,%1,%2,%3};\n"
        : "+f"(c[0]), "+f"(c[1]), "+f"(c[2]), "+f"(c[3])
        : "r"(a[0]), "r"(a[1]), "r"(a[2]), "r"(a[3]), "r"(b[0]), "r"(b[1]));
}
__device__ __forceinline__ void ldsm4(uint32_t& r0, uint32_t& r1,
                                      uint32_t& r2, uint32_t& r3, uint32_t addr)
{
    asm volatile("ldmatrix.sync.aligned.m8n8.x4.shared.b16 {%0,%1,%2,%3}, [%4];"
                 : "=r"(r0), "=r"(r1), "=r"(r2), "=r"(r3) : "r"(addr));
}
__device__ __forceinline__ void ldsm4t(uint32_t& r0, uint32_t& r1,
                                       uint32_t& r2, uint32_t& r3, uint32_t addr)
{
    asm volatile("ldmatrix.sync.aligned.m8n8.x4.trans.shared.b16 {%0,%1,%2,%3}, [%4];"
                 : "=r"(r0), "=r"(r1), "=r"(r2), "=r"(r3) : "r"(addr));
}

// ---------------------------------------------------------------------------
// Weight pack: hi plane only (fp16 round)
// ---------------------------------------------------------------------------
__global__ void __launch_bounds__(256) pack_weights_kernel(
    const float* __restrict__ W, ushort_t* __restrict__ Ph, int n)
{
    int i = blockIdx.x * 256 + threadIdx.x;
    if (i < n) {
        __half hb = __float2half_rn(W[i]);
        ushort_t h; memcpy(&h, &hb, 2);
        Ph[i] = h;
    }
}

// ---------------------------------------------------------------------------
template<bool IN_CM>
__global__ void __launch_bounds__(256) dwconv_res_kernel(
    const float* __restrict__ x, const float* __restrict__ w,
    const float* __restrict__ bias, float* __restrict__ out,
    ushort_t* __restrict__ oh, ushort_t* __restrict__ ol)
{
    int bc = blockIdx.y;
    int c = bc & (ED - 1);
    int b = bc >> 9;
    int pos = blockIdx.x * 256 + threadIdx.x;
    if (pos >= HW) return;
    int h = pos / RES, ww = pos % RES;
    const float* xp = IN_CM ? (x + (size_t)c * NTOT + (size_t)b * HW)
                            : (x + (size_t)bc * HW);
    const float* wp = w + c * 9;
    float acc = bias[c];
#pragma unroll
    for (int dy = 0; dy < 3; dy++) {
        int yy = h + dy - 1;
        if (yy < 0 || yy >= RES) continue;
#pragma unroll
        for (int dx = 0; dx < 3; dx++) {
            int xx = ww + dx - 1;
            if (xx < 0 || xx >= RES) continue;
            acc += xp[yy * RES + xx] * wp[dy * 3 + dx];
        }
    }
    float r = xp[pos] + acc;
    size_t o = (size_t)c * NTOT + (size_t)b * HW + pos;
    out[o] = r;
    ushort_t hh, ll;
    split2(r, hh, ll);
    oh[o] = hh; ol[o] = ll;
}

// ---------------------------------------------------------------------------
// HMMA GEMM, CTA 128x128, K-chunk 32, cp.async double buffer.
// fp16 asymmetric split: A = weights (hi only), B = activations (hi+lo).
// 2 mma passes: acc += ah*bh + ah*bl.
// Stage layout (24KB): Ah 0 | Bh 8K | Bl 16K. Two stages = 48KB.
// ---------------------------------------------------------------------------
template<int MODE>
__global__ void __launch_bounds__(256, 2) gemm_cp_kernel(
    const ushort_t* __restrict__ Awh,
    const ushort_t* __restrict__ Bh,  const ushort_t* __restrict__ Bl,
    const float* __restrict__ bias, const float* __restrict__ resid,
    float* __restrict__ Cf, ushort_t* __restrict__ Chh, ushort_t* __restrict__ Chl,
    int M, int NB, int K)
{
    extern __shared__ char sm[];
    int t = threadIdx.x;
    int warp = t >> 5, lane = t & 31;
    int wm = warp & 1, wn = warp >> 1;
    int m0w = wm * 64, n0w = wn * 32;
    int g = lane >> 2, tig = lane & 3;
    int m0 = blockIdx.y * 128, n0 = blockIdx.x * 128;
    uint32_t sbase = smem_u32(sm);

    float acc[4][4][4];
#pragma unroll
    for (int i = 0; i < 4; i++)
#pragma unroll
        for (int j = 0; j < 4; j++)
#pragma unroll
            for (int q = 0; q < 4; q++) acc[i][j][q] = 0.f;

    auto stage = [&](int k0, int buf) {
        uint32_t soff = sbase + buf * 24576;
        // A hi: 128 m x 32 k = 512 x 16B
#pragma unroll
        for (int i = 0; i < 2; i++) {
            int idx = t + i * 256;
            int m = idx >> 2, c = idx & 3;
            uint32_t d = soff + m * 64 + ((c ^ ((m >> 1) & 3)) << 4);
            cpasync16(d, Awh + (size_t)(m0 + m) * K + k0 + c * 8);
        }
        // B hi+lo: 32 k x 128 n = 512 x 16B each
#pragma unroll
        for (int i = 0; i < 2; i++) {
            int idx = t + i * 256;
            int k = idx >> 4, c = idx & 15;
            uint32_t d = soff + 8192 + k * 256 + ((c ^ (k & 7)) << 4);
            cpasync16(d, Bh + (size_t)(k0 + k) * NB + n0 + c * 8);
            cpasync16(d + 8192, Bl + (size_t)(k0 + k) * NB + n0 + c * 8);
        }
        asm volatile("cp.async.commit_group;" ::: "memory");
    };

    stage(0, 0);
    int nk = K >> 5;
    for (int kc = 0; kc < nk; kc++) {
        if (kc + 1 < nk) {
            stage((kc + 1) << 5, (kc + 1) & 1);
            asm volatile("cp.async.wait_group 1;" ::: "memory");
        } else {
            asm volatile("cp.async.wait_group 0;" ::: "memory");
        }
        __syncthreads();
        uint32_t soff = sbase + (kc & 1) * 24576;
#pragma unroll
        for (int kk = 0; kk < 32; kk += 16) {
            uint32_t bh[4][2], bl[4][2];
#pragma unroll
            for (int j2 = 0; j2 < 2; j2++) {
                int krow = kk + (lane & 15);
                int cn = wn * 4 + j2 * 2 + (lane >> 4);
                uint32_t a = soff + 8192 + krow * 256 + ((cn ^ (krow & 7)) << 4);
                ldsm4t(bh[j2*2][0], bh[j2*2][1], bh[j2*2+1][0], bh[j2*2+1][1], a);
                ldsm4t(bl[j2*2][0], bl[j2*2][1], bl[j2*2+1][0], bl[j2*2+1][1], a + 8192);
            }
#pragma unroll
            for (int i = 0; i < 4; i++) {
                int row = m0w + i * 16 + (lane & 15);
                int c = (kk >> 3) + (lane >> 4);
                uint32_t a = soff + row * 64 + ((c ^ ((row >> 1) & 3)) << 4);
                uint32_t ah[4];
                ldsm4(ah[0], ah[1], ah[2], ah[3], a);
#pragma unroll
                for (int j = 0; j < 4; j++) {
                    mma_f16(acc[i][j], ah, bh[j]);
                    mma_f16(acc[i][j], ah, bl[j]);
                }
            }
        }
        __syncthreads();
    }

    // Epilogue
#pragma unroll
    for (int i = 0; i < 4; i++) {
        int r0 = m0 + m0w + i * 16 + g;
        int r1 = r0 + 8;
        float b0v = bias[r0], b1v = bias[r1];
#pragma unroll
        for (int j = 0; j < 4; j++) {
            int cb = n0 + n0w + j * 8 + tig * 2;
            float v00 = acc[i][j][0] + b0v, v01 = acc[i][j][1] + b0v;
            float v10 = acc[i][j][2] + b1v, v11 = acc[i][j][3] + b1v;
            if (MODE == 0) {
                ushort_t h0, l0, h1, l1;
                split2(hswish(v00), h0, l0);
                split2(hswish(v01), h1, l1);
                *(uint32_t*)&Chh[(size_t)r0 * NB + cb] = (uint32_t)h0 | ((uint32_t)h1 << 16);
                *(uint32_t*)&Chl[(size_t)r0 * NB + cb] = (uint32_t)l0 | ((uint32_t)l1 << 16);
                split2(hswish(v10), h0, l0);
                split2(hswish(v11), h1, l1);
                *(uint32_t*)&Chh[(size_t)r1 * NB + cb] = (uint32_t)h0 | ((uint32_t)h1 << 16);
                *(uint32_t*)&Chl[(size_t)r1 * NB + cb] = (uint32_t)l0 | ((uint32_t)l1 << 16);
            } else if (MODE == 1) {
                size_t o0 = (size_t)r0 * NB + cb;
                size_t o1 = (size_t)r1 * NB + cb;
                float2 rr0 = *(const float2*)&resid[o0];
                float2 rr1 = *(const float2*)&resid[o1];
                *(float2*)&Cf[o0] = make_float2(v00 + rr0.x, v01 + rr0.y);
                *(float2*)&Cf[o1] = make_float2(v10 + rr1.x, v11 + rr1.y);
            } else if (MODE == 2) {
                float vs[4] = {v00, v01, v10, v11};
#pragma unroll
                for (int q = 0; q < 4; q++) {
                    int col = cb + (q & 1);
                    int r = (q < 2) ? r0 : r1;
                    int win = col / NTOKP, tok = col % NTOKP;
                    if (tok < NTOK) {
                        int b = win >> 4, wy = (win >> 2) & 3, wx = win & 3;
                        int iy = tok / WS, ix = tok % WS;
                        size_t o = (size_t)r * NTOT + (size_t)b * HW
                                 + (wy * WS + iy) * RES + (wx * WS + ix);
                        Cf[o] = Cf[o] + vs[q];
                    }
                }
            } else {
                int b = cb / HW, pos = cb % HW;
                size_t o0 = (size_t)r0 * NB + cb;
                size_t o1 = (size_t)r1 * NB + cb;
                float2 rr0 = *(const float2*)&resid[o0];
                float2 rr1 = *(const float2*)&resid[o1];
                *(float2*)&Cf[((size_t)b * ED + r0) * HW + pos] =
                    make_float2(v00 + rr0.x, v01 + rr0.y);
                *(float2*)&Cf[((size_t)b * ED + r1) * HW + pos] =
                    make_float2(v10 + rr1.x, v11 + rr1.y);
            }
        }
    }
}

// ---------------------------------------------------------------------------
// Cascaded window attention (vectorized; outputs fp16 hi/lo planes)
// ---------------------------------------------------------------------------
#define SP_OFF   0
#define Y_OFF    (SP_OFF + 49 * 68)
#define KT_OFF   (Y_OFF + 96 * 52)
#define QT_OFF   (KT_OFF + 49 * 20)
#define ATT_OFF  (QT_OFF + 49 * 20)
#define WSM_OFF  (ATT_OFF + 49 * 52)
#define BSM_OFF  (WSM_OFF + 96 * 68)
#define BIA_OFF  (BSM_OFF + 96)
#define ATTN_SMEM_FLOATS (BIA_OFF + 64)
#define ATTN_SMEM_BYTES  (ATTN_SMEM_FLOATS * 4)

__global__ void __launch_bounds__(256) attn_kernel(
    const float* __restrict__ xin,
    const float* __restrict__ qkv_w,
    const float* __restrict__ qkv_b,
    const float* __restrict__ w7, const float* __restrict__ b7,
    const float* __restrict__ w5, const float* __restrict__ b5,
    const float* __restrict__ w3, const float* __restrict__ b3,
    const float* __restrict__ attn_bias,
    ushort_t* __restrict__ oh, ushort_t* __restrict__ ol)
{
    extern __shared__ float smem[];
    float* spT = smem + SP_OFF;
    float* y   = smem + Y_OFF;
    float* kT  = smem + KT_OFF;
    float* qcT = smem + QT_OFF;
    float* att = smem + ATT_OFF;
    float* wsm = smem + WSM_OFF;
    float* bsm = smem + BSM_OFF;
    float* bia = smem + BIA_OFF;

    int w = blockIdx.x;
    int b = w >> 4, wy = (w >> 2) & 3, wx = w & 3;
    int t = threadIdx.x;
    int warp = t >> 5, lane = t & 31;

    for (int i = t; i < 96 * 3; i += 256)
        y[(i / 3) * 52 + 49 + i % 3] = 0.f;

    for (int head = 0; head < NH; head++) {
        for (int i = t; i < QKV_OUT * DHEAD; i += 256) {
            int m = i >> 6, c = i & 63;
            wsm[m * 68 + c] = qkv_w[head * QKV_OUT * DHEAD + i];
        }
        if (t < QKV_OUT) bsm[t] = qkv_b[head * QKV_OUT + t];
        if (t < NTOK)    bia[t] = attn_bias[head * NTOK + t];
        for (int i = t; i < DHEAD * NTOK; i += 256) {
            int c = i / NTOK, n = i % NTOK;
            int iy = n / WS, ix = n % WS;
            float xv = xin[(size_t)(head * DHEAD + c) * NTOT + (size_t)b * HW
                           + (wy * WS + iy) * RES + (wx * WS + ix)];
            spT[n * 68 + c] = (head == 0) ? xv : spT[n * 68 + c] + xv;
        }
        __syncthreads();

        // QKV
        for (int it = t; it < 13 * 96; it += 256) {
            int gq = it / 96, m = it % 96;
            int n0 = gq * 4;
            float a0 = bsm[m], a1 = a0, a2 = a0, a3 = a0;
            const float* wr = &wsm[m * 68];
#pragma unroll
            for (int c4 = 0; c4 < 16; c4++) {
                float4 wv = *(const float4*)&wr[c4 * 4];
                float4 s0 = *(const float4*)&spT[(n0 + 0) * 68 + c4 * 4];
                float4 s1 = *(const float4*)&spT[(n0 + 1) * 68 + c4 * 4];
                float4 s2 = *(const float4*)&spT[(n0 + 2) * 68 + c4 * 4];
                float4 s3 = *(const float4*)&spT[(n0 + 3) * 68 + c4 * 4];
                a0 += wv.x * s0.x + wv.y * s0.y + wv.z * s0.z + wv.w * s0.w;
                a1 += wv.x * s1.x + wv.y * s1.y + wv.z * s1.z + wv.w * s1.w;
                a2 += wv.x * s2.x + wv.y * s2.y + wv.z * s2.z + wv.w * s2.w;
                a3 += wv.x * s3.x + wv.y * s3.y + wv.z * s3.z + wv.w * s3.w;
            }
            float av[4] = {a0, a1, a2, a3};
#pragma unroll
            for (int j = 0; j < 4; j++) {
                int n = n0 + j;
                if (n < NTOK) {
                    y[m * 52 + n] = av[j];
                    if (m >= KD && m < 2 * KD) kT[n * 20 + m - KD] = av[j];
                }
            }
        }
        __syncthreads();

        // depthwise conv on q
        int ksz; const float* dw; const float* db;
        if (head == 0)      { ksz = 7; dw = w7; db = b7; }
        else if (head == 1) { ksz = 5; dw = w5; db = b5; }
        else                { ksz = 3; dw = w3 + (head - 2) * KD * 9; db = b3 + (head - 2) * KD; }
        int pad = ksz >> 1;
        for (int it = t; it < KD * NTOK; it += 256) {
            int c = it / NTOK, n = it % NTOK;
            int iy = n / WS, ix = n % WS;
            float acc = db[c];
            const float* yr = &y[c * 52];
            const float* dwc = dw + c * ksz * ksz;
            for (int dy = 0; dy < ksz; dy++) {
                int yy = iy + dy - pad;
                if (yy < 0 || yy >= WS) continue;
                for (int dx = 0; dx < ksz; dx++) {
                    int xx = ix + dx - pad;
                    if (xx < 0 || xx >= WS) continue;
                    acc += yr[yy * WS + xx] * dwc[dy * ksz + dx];
                }
            }
            qcT[n * 20 + c] = acc;
        }
        __syncthreads();

        // scores
        for (int it = t; it < 49 * 52; it += 256) {
            int n = it / 52, m = it % 52;
            if (m >= NTOK) { att[it] = 0.f; continue; }
            const float* qr = &qcT[n * 20];
            const float* kr = &kT[m * 20];
            float acc = 0.f;
#pragma unroll
            for (int c4 = 0; c4 < 4; c4++) {
                float4 qv = *(const float4*)&qr[c4 * 4];
                float4 kv = *(const float4*)&kr[c4 * 4];
                acc += qv.x * kv.x + qv.y * kv.y + qv.z * kv.z + qv.w * kv.w;
            }
            int ny = n / WS, nx = n % WS, my = m / WS, mx = m % WS;
            att[it] = acc * 0.25f + bia[abs(ny - my) * WS + abs(nx - mx)];
        }
        __syncthreads();

        // softmax: warp per row
        for (int r = warp; r < NTOK; r += 8) {
            float v0 = att[r * 52 + lane];
            float v1 = (lane + 32 < NTOK) ? att[r * 52 + lane + 32] : -1e30f;
            float mx = fmaxf(v0, v1);
#pragma unroll
            for (int s = 16; s; s >>= 1) mx = fmaxf(mx, __shfl_xor_sync(~0u, mx, s));
            float e0 = expf(v0 - mx);
            float e1 = (lane + 32 < NTOK) ? expf(v1 - mx) : 0.f;
            float sum = e0 + e1;
#pragma unroll
            for (int s = 16; s; s >>= 1) sum += __shfl_xor_sync(~0u, sum, s);
            float inv = 1.f / sum;
            att[r * 52 + lane] = e0 * inv;
            if (lane + 32 < NTOK) att[r * 52 + lane + 32] = e1 * inv;
        }
        __syncthreads();

        // AV
        size_t obase = (size_t)(head * DHEAD) * NPROJ + (size_t)w * NTOKP;
        for (int it = t; it < 16 * NTOK; it += 256) {
            int dg = it / NTOK, n = it % NTOK;
            int d0 = dg * 4;
            float a0 = 0.f, a1 = 0.f, a2 = 0.f, a3 = 0.f;
            const float* ar = &att[n * 52];
#pragma unroll
            for (int m4 = 0; m4 < 13; m4++) {
                float4 av = *(const float4*)&ar[m4 * 4];
                float4 v0 = *(const float4*)&y[(32 + d0 + 0) * 52 + m4 * 4];
                float4 v1 = *(const float4*)&y[(32 + d0 + 1) * 52 + m4 * 4];
                float4 v2 = *(const float4*)&y[(32 + d0 + 2) * 52 + m4 * 4];
                float4 v3 = *(const float4*)&y[(32 + d0 + 3) * 52 + m4 * 4];
                a0 += av.x * v0.x + av.y * v0.y + av.z * v0.z + av.w * v0.w;
                a1 += av.x * v1.x + av.y * v1.y + av.z * v1.z + av.w * v1.w;
                a2 += av.x * v2.x + av.y * v2.y + av.z * v2.z + av.w * v2.w;
                a3 += av.x * v3.x + av.y * v3.y + av.z * v3.z + av.w * v3.w;
            }
            float av4[4] = {a0, a1, a2, a3};
#pragma unroll
            for (int jj = 0; jj < 4; jj++) {
                int d = d0 + jj;
                spT[n * 68 + d] = av4[jj];
                ushort_t hh, ll;
                split2(hswish(av4[jj]), hh, ll);
                oh[obase + (size_t)d * NPROJ + n] = hh;
                ol[obase + (size_t)d * NPROJ + n] = ll;
            }
        }
        for (int it = t; it < DHEAD * (NTOKP - NTOK); it += 256) {
            int p = it / DHEAD, d = it % DHEAD;
            oh[obase + (size_t)d * NPROJ + NTOK + p] = 0;
            ol[obase + (size_t)d * NPROJ + NTOK + p] = 0;
        }
        __syncthreads();
    }
}

// ---------------------------------------------------------------------------
extern "C" void kernel_launch(void* const* d_in, const int* in_sizes, int n_in,
                              void* d_out, int out_size)
{
    const float* x        = (const float*)d_in[0];
    const float* dw0_w    = (const float*)d_in[1];
    const float* dw0_b    = (const float*)d_in[2];
    const float* ffn0_w1  = (const float*)d_in[3];
    const float* ffn0_b1  = (const float*)d_in[4];
    const float* ffn0_w2  = (const float*)d_in[5];
    const float* ffn0_b2  = (const float*)d_in[6];
    const float* qkv_w    = (const float*)d_in[7];
    const float* qkv_b    = (const float*)d_in[8];
    const float* dwq_w7   = (const float*)d_in[9];
    const float* dwq_b7   = (const float*)d_in[10];
    const float* dwq_w5   = (const float*)d_in[11];
    const float* dwq_b5   = (const float*)d_in[12];
    const float* dwq_w3   = (const float*)d_in[13];
    const float* dwq_b3   = (const float*)d_in[14];
    const float* attn_bias= (const float*)d_in[15];
    const float* proj_w   = (const float*)d_in[16];
    const float* proj_b   = (const float*)d_in[17];
    const float* dw1_w    = (const float*)d_in[18];
    const float* dw1_b    = (const float*)d_in[19];
    const float* ffn1_w1  = (const float*)d_in[20];
    const float* ffn1_b1  = (const float*)d_in[21];
    const float* ffn1_w2  = (const float*)d_in[22];
    const float* ffn1_b2  = (const float*)d_in[23];

    float *paf, *pbf;
    ushort_t *pah, *pal, *phh, *phl, *pch, *pcl;
    ushort_t *pw1h, *pw2h, *pw1bh, *pw2bh, *ppjh;
    cudaGetSymbolAddress((void**)&paf, g_af);
    cudaGetSymbolAddress((void**)&pbf, g_bf);
    cudaGetSymbolAddress((void**)&pah, g_ah);
    cudaGetSymbolAddress((void**)&pal, g_al);
    cudaGetSymbolAddress((void**)&phh, g_hh);
    cudaGetSymbolAddress((void**)&phl, g_hl);
    cudaGetSymbolAddress((void**)&pch, g_ch);
    cudaGetSymbolAddress((void**)&pcl, g_cl);
    cudaGetSymbolAddress((void**)&pw1h, g_w1h);
    cudaGetSymbolAddress((void**)&pw2h, g_w2h);
    cudaGetSymbolAddress((void**)&pw1bh, g_w1bh);
    cudaGetSymbolAddress((void**)&pw2bh, g_w2bh);
    cudaGetSymbolAddress((void**)&ppjh, g_pjh);

    cudaFuncSetAttribute(attn_kernel, cudaFuncAttributeMaxDynamicSharedMemorySize, ATTN_SMEM_BYTES);
    cudaFuncSetAttribute(gemm_cp_kernel<0>, cudaFuncAttributeMaxDynamicSharedMemorySize, 49152);
    cudaFuncSetAttribute(gemm_cp_kernel<1>, cudaFuncAttributeMaxDynamicSharedMemorySize, 49152);
    cudaFuncSetAttribute(gemm_cp_kernel<2>, cudaFuncAttributeMaxDynamicSharedMemorySize, 49152);
    cudaFuncSetAttribute(gemm_cp_kernel<3>, cudaFuncAttributeMaxDynamicSharedMemorySize, 49152);

    // Weight pack (hi plane only)
    pack_weights_kernel<<<2048, 256>>>(ffn0_w1, pw1h, 1024 * 512);
    pack_weights_kernel<<<2048, 256>>>(ffn0_w2, pw2h, 512 * 1024);
    pack_weights_kernel<<<2048, 256>>>(ffn1_w1, pw1bh, 1024 * 512);
    pack_weights_kernel<<<2048, 256>>>(ffn1_w2, pw2bh, 512 * 1024);
    pack_weights_kernel<<<1024, 256>>>(proj_w, ppjh, 512 * 512);

    dim3 dwgrid((HW + 255) / 256, BATCH * ED);

    dwconv_res_kernel<false><<<dwgrid, 256>>>(x, dw0_w, dw0_b, paf, pah, pal);
    gemm_cp_kernel<0><<<dim3(NTOT / 128, 8), 256, 49152>>>(
        pw1h, pah, pal, ffn0_b1, nullptr, nullptr, phh, phl, 1024, NTOT, 512);
    gemm_cp_kernel<1><<<dim3(NTOT / 128, 4), 256, 49152>>>(
        pw2h, phh, phl, ffn0_b2, paf, pbf, nullptr, nullptr, 512, NTOT, 1024);
    attn_kernel<<<NW_TOT, 256, ATTN_SMEM_BYTES>>>(pbf, qkv_w, qkv_b, dwq_w7, dwq_b7,
        dwq_w5, dwq_b5, dwq_w3, dwq_b3, attn_bias, pch, pcl);
    gemm_cp_kernel<2><<<dim3(NPROJ / 128, 4), 256, 49152>>>(
        ppjh, pch, pcl, proj_b, nullptr, pbf, nullptr, nullptr, 512, NPROJ, 512);
    dwconv_res_kernel<true><<<dwgrid, 256>>>(pbf, dw1_w, dw1_b, paf, pah, pal);
    gemm_cp_kernel<0><<<dim3(NTOT / 128, 8), 256, 49152>>>(
        pw1bh, pah, pal, ffn1_b1, nullptr, nullptr, phh, phl, 1024, NTOT, 512);
    gemm_cp_kernel<3><<<dim3(NTOT / 128, 4), 256, 49152>>>(
        pw2bh, phh, phl, ffn1_b2, paf, (float*)d_out, nullptr, nullptr, 512, NTOT, 1024);
}